// round 5
// baseline (speedup 1.0000x reference)
#include <cuda_runtime.h>
#include <cuda_bf16.h>
#include <math.h>

// DirectAU loss: align + uniformity on N=8192, D=64 fp32 vectors.
//   align   = mean_i ||u_hat_i - i_hat_i||^2
//   uniform = (log(2*S_u/(N(N-1)) + eps) + log(2*S_i/(N(N-1)) + eps)) / 2
//   where S = sum_{i>j} exp(-2 * max(2 - 2 <x_i, x_j>, 0))   (strict lower tri)
// (full symmetric Gram sum = 2S + N diag terms, matching the reference)

#define NROWS 8192
#define DDIM  64
#define TILE  128
#define NTILES 64              // NROWS / TILE
#define NPAIRS 2080            // NTILES*(NTILES+1)/2
#define T_COEF 2.0f
#define EPS_U  1e-8f

__device__ float g_U[NROWS * DDIM];
__device__ float g_I[NROWS * DDIM];
__device__ float g_align[NROWS];
__device__ float g_S[2 * NPAIRS];

// ---------------------------------------------------------------------------
// Kernel 1: normalize both matrices + per-row alignment term.
// 256 threads = 8 warps, one warp per row (each lane holds a float2 = 2 elems).
// ---------------------------------------------------------------------------
__global__ void __launch_bounds__(256) k_norm_align(const float* __restrict__ U,
                                                    const float* __restrict__ I)
{
    int warp = threadIdx.x >> 5;
    int lane = threadIdx.x & 31;
    int row  = blockIdx.x * 8 + warp;

    float2 u = ((const float2*)U)[row * 32 + lane];
    float2 v = ((const float2*)I)[row * 32 + lane];

    float su = u.x * u.x + u.y * u.y;
    float sv = v.x * v.x + v.y * v.y;
    #pragma unroll
    for (int o = 16; o > 0; o >>= 1) {
        su += __shfl_xor_sync(0xffffffffu, su, o);
        sv += __shfl_xor_sync(0xffffffffu, sv, o);
    }
    // rsqrt + one Newton iteration for near-fp32-exact inverse norm
    float ru = rsqrtf(su); ru = ru * (1.5f - 0.5f * su * ru * ru);
    float rv = rsqrtf(sv); rv = rv * (1.5f - 0.5f * sv * rv * rv);

    float2 un = make_float2(u.x * ru, u.y * ru);
    float2 vn = make_float2(v.x * rv, v.y * rv);

    ((float2*)g_U)[row * 32 + lane] = un;
    ((float2*)g_I)[row * 32 + lane] = vn;

    float dx = un.x - vn.x, dy = un.y - vn.y;
    float a = dx * dx + dy * dy;
    #pragma unroll
    for (int o = 16; o > 0; o >>= 1)
        a += __shfl_xor_sync(0xffffffffu, a, o);
    if (lane == 0) g_align[row] = a;
}

// ---------------------------------------------------------------------------
// Kernel 2: pairwise exp-sum over one 128x128 tile-pair of the Gram.
// grid = (NPAIRS, 2). Triangular tile enumeration (bi >= bj). Diagonal tiles
// mask to j < i. 256 threads, 8x8 microtile per thread, K chunked by 32.
// Shared rows padded to 36 floats: keeps LDS.128 rows 16B-aligned and makes
// the strided-j B-fragment loads at most 2-way bank conflicted.
// ---------------------------------------------------------------------------
__global__ void __launch_bounds__(256, 1) k_pair()
{
    const int t   = blockIdx.x;
    const int mat = blockIdx.y;
    const float* __restrict__ X = mat ? g_I : g_U;

    // map t -> (bi, bj), bi >= bj, t = bi*(bi+1)/2 + bj
    int bi = (int)((sqrtf(8.0f * (float)t + 1.0f) - 1.0f) * 0.5f);
    while ((bi + 1) * (bi + 2) / 2 <= t) ++bi;
    while (bi * (bi + 1) / 2 > t) --bi;
    int bj = t - bi * (bi + 1) / 2;
    const bool diag = (bi == bj);

    __shared__ float As[TILE][36];
    __shared__ float Bs[TILE][36];
    __shared__ float red[256];

    const int tid = threadIdx.x;
    const int tx  = tid & 15;   // j dimension (strided by 16)
    const int ty  = tid >> 4;   // i dimension (contiguous groups of 8)

    const int ibase = bi * TILE;
    const int jbase = bj * TILE;

    float acc[8][8];
    #pragma unroll
    for (int m = 0; m < 8; ++m)
        #pragma unroll
        for (int n = 0; n < 8; ++n) acc[m][n] = 0.0f;

    #pragma unroll
    for (int k0 = 0; k0 < DDIM; k0 += 32) {
        // load 128x32 chunks of A and B (float4 per thread x4)
        #pragma unroll
        for (int r = 0; r < 4; ++r) {
            int idx = tid + 256 * r;        // 0..1023
            int row = idx >> 3;             // 0..127
            int c4  = (idx & 7) << 2;       // 0,4,...,28
            float4 va = *(const float4*)&X[(ibase + row) * DDIM + k0 + c4];
            *(float4*)&As[row][c4] = va;
            float4 vb = *(const float4*)&X[(jbase + row) * DDIM + k0 + c4];
            *(float4*)&Bs[row][c4] = vb;
        }
        __syncthreads();

        #pragma unroll
        for (int k = 0; k < 32; k += 4) {
            float4 a[8], b[8];
            #pragma unroll
            for (int m = 0; m < 8; ++m)
                a[m] = *(const float4*)&As[ty * 8 + m][k];
            #pragma unroll
            for (int n = 0; n < 8; ++n)
                b[n] = *(const float4*)&Bs[tx + 16 * n][k];
            #pragma unroll
            for (int m = 0; m < 8; ++m)
                #pragma unroll
                for (int n = 0; n < 8; ++n) {
                    acc[m][n] = fmaf(a[m].x, b[n].x, acc[m][n]);
                    acc[m][n] = fmaf(a[m].y, b[n].y, acc[m][n]);
                    acc[m][n] = fmaf(a[m].z, b[n].z, acc[m][n]);
                    acc[m][n] = fmaf(a[m].w, b[n].w, acc[m][n]);
                }
        }
        __syncthreads();
    }

    // epilogue: exp(-T*max(2-2d,0)) = exp(4*min(d,1) - 4) with T=2
    float s = 0.0f;
    #pragma unroll
    for (int m = 0; m < 8; ++m) {
        int gi = ibase + ty * 8 + m;
        #pragma unroll
        for (int n = 0; n < 8; ++n) {
            int gj = jbase + tx + 16 * n;
            float d = acc[m][n];
            float term = __expf(fminf(d, 1.0f) * 4.0f - 4.0f);
            if (!diag || gj < gi) s += term;
        }
    }

    // deterministic block tree-reduction
    red[tid] = s;
    __syncthreads();
    #pragma unroll
    for (int o = 128; o > 0; o >>= 1) {
        if (tid < o) red[tid] += red[tid + o];
        __syncthreads();
    }
    if (tid == 0) g_S[mat * NPAIRS + t] = red[0];
}

// ---------------------------------------------------------------------------
// Kernel 3: deterministic final reduction + scalar assembly.
// ---------------------------------------------------------------------------
__device__ __forceinline__ float block_sum(const float* src, int n,
                                           float* red, int tid)
{
    float a = 0.0f;
    for (int i = tid; i < n; i += 256) a += src[i];
    red[tid] = a;
    __syncthreads();
    #pragma unroll
    for (int o = 128; o > 0; o >>= 1) {
        if (tid < o) red[tid] += red[tid + o];
        __syncthreads();
    }
    float r = red[0];
    __syncthreads();
    return r;
}

__global__ void k_final(float* __restrict__ out)
{
    __shared__ float red[256];
    int tid = threadIdx.x;

    float align_sum = block_sum(g_align, NROWS, red, tid);
    float su        = block_sum(g_S, NPAIRS, red, tid);
    float si        = block_sum(g_S + NPAIRS, NPAIRS, red, tid);

    if (tid == 0) {
        const float denom = (float)NROWS * (float)(NROWS - 1);
        float align  = align_sum / (float)NROWS;
        float log_u  = logf(2.0f * su / denom + EPS_U);
        float log_i  = logf(2.0f * si / denom + EPS_U);
        out[0] = align + 0.5f * (log_u + log_i);   // GAMMA = 1
    }
}

extern "C" void kernel_launch(void* const* d_in, const int* in_sizes, int n_in,
                              void* d_out, int out_size)
{
    const float* U = (const float*)d_in[0];
    const float* I = (const float*)d_in[1];
    float* out = (float*)d_out;

    k_norm_align<<<NROWS / 8, 256>>>(U, I);
    dim3 grid(NPAIRS, 2, 1);
    k_pair<<<grid, 256>>>();
    k_final<<<1, 256>>>(out);
}

// round 6
// speedup vs baseline: 1.0921x; 1.0921x over previous
#include <cuda_runtime.h>
#include <cuda_bf16.h>
#include <math.h>

// DirectAU loss: align + uniformity on N=8192, D=64 fp32 vectors.
//   align   = mean_i ||u_hat_i - i_hat_i||^2
//   uniform = (log(2*S_u/(N(N-1)) + eps) + log(2*S_i/(N(N-1)) + eps)) / 2
//   where S = sum_{i>j} exp(-2 * max(2 - 2 <x_i, x_j>, 0))   (strict lower tri)
//
// R5 change: Gram mainloop uses packed fma.rn.f32x2 (SASS FFMA2, PTX-only on
// Blackwell) paired over the K dimension: float4 fragments are two bit-adjacent
// (k,k+1) f32x2 pairs, so lo accumulates even-k and hi odd-k products with zero
// packing overhead. Mainloop FMA instruction count halves.

#define NROWS 8192
#define DDIM  64
#define TILE  128
#define NTILES 64              // NROWS / TILE
#define NPAIRS 2080            // NTILES*(NTILES+1)/2
#define EPS_U  1e-8f

__device__ float g_U[NROWS * DDIM];
__device__ float g_I[NROWS * DDIM];
__device__ float g_align[NROWS];
__device__ float g_S[2 * NPAIRS];

// packed dual-FMA: d.lo += a.lo*b.lo ; d.hi += a.hi*b.hi
__device__ __forceinline__ void ffma2(unsigned long long& d,
                                      unsigned long long a,
                                      unsigned long long b)
{
    asm("fma.rn.f32x2 %0, %1, %2, %0;" : "+l"(d) : "l"(a), "l"(b));
}

__device__ __forceinline__ float fold2(unsigned long long v)
{
    float lo, hi;
    asm("mov.b64 {%0,%1}, %2;" : "=f"(lo), "=f"(hi) : "l"(v));
    return lo + hi;
}

// ---------------------------------------------------------------------------
// Kernel 1: normalize both matrices + per-row alignment term.
// ---------------------------------------------------------------------------
__global__ void __launch_bounds__(256) k_norm_align(const float* __restrict__ U,
                                                    const float* __restrict__ I)
{
    int warp = threadIdx.x >> 5;
    int lane = threadIdx.x & 31;
    int row  = blockIdx.x * 8 + warp;

    float2 u = ((const float2*)U)[row * 32 + lane];
    float2 v = ((const float2*)I)[row * 32 + lane];

    float su = u.x * u.x + u.y * u.y;
    float sv = v.x * v.x + v.y * v.y;
    #pragma unroll
    for (int o = 16; o > 0; o >>= 1) {
        su += __shfl_xor_sync(0xffffffffu, su, o);
        sv += __shfl_xor_sync(0xffffffffu, sv, o);
    }
    float ru = rsqrtf(su); ru = ru * (1.5f - 0.5f * su * ru * ru);
    float rv = rsqrtf(sv); rv = rv * (1.5f - 0.5f * sv * rv * rv);

    float2 un = make_float2(u.x * ru, u.y * ru);
    float2 vn = make_float2(v.x * rv, v.y * rv);

    ((float2*)g_U)[row * 32 + lane] = un;
    ((float2*)g_I)[row * 32 + lane] = vn;

    float dx = un.x - vn.x, dy = un.y - vn.y;
    float a = dx * dx + dy * dy;
    #pragma unroll
    for (int o = 16; o > 0; o >>= 1)
        a += __shfl_xor_sync(0xffffffffu, a, o);
    if (lane == 0) g_align[row] = a;
}

// ---------------------------------------------------------------------------
// Kernel 2: pairwise exp-sum over one 128x128 tile-pair of the Gram.
// grid = (NPAIRS, 2). Triangular tile enumeration (bi >= bj); diagonal tiles
// mask to j < i. 256 threads, 8x8 microtile, K chunked by 32, FFMA2 mainloop.
// ---------------------------------------------------------------------------
__global__ void __launch_bounds__(256, 1) k_pair()
{
    const int t   = blockIdx.x;
    const int mat = blockIdx.y;
    const float* __restrict__ X = mat ? g_I : g_U;

    // map t -> (bi, bj), bi >= bj, t = bi*(bi+1)/2 + bj
    int bi = (int)((sqrtf(8.0f * (float)t + 1.0f) - 1.0f) * 0.5f);
    while ((bi + 1) * (bi + 2) / 2 <= t) ++bi;
    while (bi * (bi + 1) / 2 > t) --bi;
    int bj = t - bi * (bi + 1) / 2;
    const bool diag = (bi == bj);

    __shared__ float As[TILE][36];
    __shared__ float Bs[TILE][36];
    __shared__ float red[256];

    const int tid = threadIdx.x;
    const int tx  = tid & 15;   // j dimension (strided by 16)
    const int ty  = tid >> 4;   // i dimension (contiguous groups of 8)

    const int ibase = bi * TILE;
    const int jbase = bj * TILE;

    // packed accumulators: lo = even-k partial dot, hi = odd-k partial dot
    unsigned long long acc2[8][8];
    #pragma unroll
    for (int m = 0; m < 8; ++m)
        #pragma unroll
        for (int n = 0; n < 8; ++n) acc2[m][n] = 0ull;

    #pragma unroll
    for (int k0 = 0; k0 < DDIM; k0 += 32) {
        // load 128x32 chunks of A and B (float4 per thread x4)
        #pragma unroll
        for (int r = 0; r < 4; ++r) {
            int idx = tid + 256 * r;        // 0..1023
            int row = idx >> 3;             // 0..127
            int c4  = (idx & 7) << 2;       // 0,4,...,28
            float4 va = *(const float4*)&X[(ibase + row) * DDIM + k0 + c4];
            *(float4*)&As[row][c4] = va;
            float4 vb = *(const float4*)&X[(jbase + row) * DDIM + k0 + c4];
            *(float4*)&Bs[row][c4] = vb;
        }
        __syncthreads();

        #pragma unroll
        for (int k = 0; k < 32; k += 4) {
            // 16B fragments = two f32x2 pairs each, loaded as ulonglong2
            ulonglong2 a[8], b[8];
            #pragma unroll
            for (int m = 0; m < 8; ++m)
                a[m] = *(const ulonglong2*)&As[ty * 8 + m][k];
            #pragma unroll
            for (int n = 0; n < 8; ++n)
                b[n] = *(const ulonglong2*)&Bs[tx + 16 * n][k];
            #pragma unroll
            for (int m = 0; m < 8; ++m)
                #pragma unroll
                for (int n = 0; n < 8; ++n) {
                    ffma2(acc2[m][n], a[m].x, b[n].x);
                    ffma2(acc2[m][n], a[m].y, b[n].y);
                }
        }
        __syncthreads();
    }

    // epilogue: exp(-T*max(2-2d,0)) = exp(4*min(d,1) - 4) with T=2
    float s = 0.0f;
    #pragma unroll
    for (int m = 0; m < 8; ++m) {
        int gi = ibase + ty * 8 + m;
        #pragma unroll
        for (int n = 0; n < 8; ++n) {
            int gj = jbase + tx + 16 * n;
            float d = fold2(acc2[m][n]);
            float term = __expf(fminf(d, 1.0f) * 4.0f - 4.0f);
            if (!diag || gj < gi) s += term;
        }
    }

    // deterministic block tree-reduction
    red[tid] = s;
    __syncthreads();
    #pragma unroll
    for (int o = 128; o > 0; o >>= 1) {
        if (tid < o) red[tid] += red[tid + o];
        __syncthreads();
    }
    if (tid == 0) g_S[mat * NPAIRS + t] = red[0];
}

// ---------------------------------------------------------------------------
// Kernel 3: deterministic final reduction + scalar assembly.
// ---------------------------------------------------------------------------
__device__ __forceinline__ float block_sum(const float* src, int n,
                                           float* red, int tid)
{
    float a = 0.0f;
    for (int i = tid; i < n; i += 256) a += src[i];
    red[tid] = a;
    __syncthreads();
    #pragma unroll
    for (int o = 128; o > 0; o >>= 1) {
        if (tid < o) red[tid] += red[tid + o];
        __syncthreads();
    }
    float r = red[0];
    __syncthreads();
    return r;
}

__global__ void k_final(float* __restrict__ out)
{
    __shared__ float red[256];
    int tid = threadIdx.x;

    float align_sum = block_sum(g_align, NROWS, red, tid);
    float su        = block_sum(g_S, NPAIRS, red, tid);
    float si        = block_sum(g_S + NPAIRS, NPAIRS, red, tid);

    if (tid == 0) {
        const float denom = (float)NROWS * (float)(NROWS - 1);
        float align  = align_sum / (float)NROWS;
        float log_u  = logf(2.0f * su / denom + EPS_U);
        float log_i  = logf(2.0f * si / denom + EPS_U);
        out[0] = align + 0.5f * (log_u + log_i);   // GAMMA = 1
    }
}

extern "C" void kernel_launch(void* const* d_in, const int* in_sizes, int n_in,
                              void* d_out, int out_size)
{
    const float* U = (const float*)d_in[0];
    const float* I = (const float*)d_in[1];
    float* out = (float*)d_out;

    k_norm_align<<<NROWS / 8, 256>>>(U, I);
    dim3 grid(NPAIRS, 2, 1);
    k_pair<<<grid, 256>>>();
    k_final<<<1, 256>>>(out);
}

// round 8
// speedup vs baseline: 4.2301x; 3.8733x over previous
#include <cuda_runtime.h>
#include <cuda_fp16.h>
#include <math.h>
#include <cstdint>

// DirectAU loss: align + uniformity on N=8192, D=64 fp32 vectors.
//   align   = mean_i ||u_hat_i - i_hat_i||^2
//   uniform = (log(2*S_u/(N(N-1)) + eps) + log(2*S_i/(N(N-1)) + eps)) / 2
//   where S = sum_{i>j} exp(-2 * max(2 - 2 <x_i, x_j>, 0))
//
// R7: tcgen05 is unavailable (harness PTX target is compute_103, which rejects
// arch-specific instructions). Gram moved to the tensor pipe via baseline
// mma.sync.m16n8k16 fp16 (HMMA) + ldmatrix instead. Single-pass fp16 is
// accurate enough: dot error ~2.5e-5 rms -> ~1e-4 zero-mean perturbation per
// exp term -> ~5e-5 rel on the final scalar (budget 1e-3).

#define NROWS  8192
#define DDIM   64
#define TILE   128
#define NTILES 64
#define NPAIRS 2080            // NTILES*(NTILES+1)/2
#define EPS_U  1e-8f

__device__ float g_align[NROWS];
__device__ float g_S[2 * NPAIRS];
__device__ unsigned int g_h16[2][NROWS * 32];   // fp16x2-packed normalized rows

// ---------------------------------------------------------------------------
// PTX helpers
// ---------------------------------------------------------------------------
__device__ __forceinline__ void ldsm4(uint32_t* r, uint32_t addr) {
    asm volatile("ldmatrix.sync.aligned.m8n8.x4.shared.b16 {%0,%1,%2,%3}, [%4];"
                 : "=r"(r[0]), "=r"(r[1]), "=r"(r[2]), "=r"(r[3]) : "r"(addr));
}
__device__ __forceinline__ void mma16816(float* d, const uint32_t* a,
                                         uint32_t b0, uint32_t b1) {
    asm volatile("mma.sync.aligned.m16n8k16.row.col.f32.f16.f16.f32 "
                 "{%0,%1,%2,%3},{%4,%5,%6,%7},{%8,%9},{%0,%1,%2,%3};"
                 : "+f"(d[0]), "+f"(d[1]), "+f"(d[2]), "+f"(d[3])
                 : "r"(a[0]), "r"(a[1]), "r"(a[2]), "r"(a[3]), "r"(b0), "r"(b1));
}

// ---------------------------------------------------------------------------
// Kernel 1: normalize both matrices, per-row alignment, fp16 pack.
// One warp per row; each lane holds a float2.
// ---------------------------------------------------------------------------
__global__ void __launch_bounds__(256) k_norm_align(const float* __restrict__ U,
                                                    const float* __restrict__ I)
{
    int warp = threadIdx.x >> 5;
    int lane = threadIdx.x & 31;
    int row  = blockIdx.x * 8 + warp;

    float2 u = ((const float2*)U)[row * 32 + lane];
    float2 v = ((const float2*)I)[row * 32 + lane];

    float su = u.x * u.x + u.y * u.y;
    float sv = v.x * v.x + v.y * v.y;
    #pragma unroll
    for (int o = 16; o > 0; o >>= 1) {
        su += __shfl_xor_sync(0xffffffffu, su, o);
        sv += __shfl_xor_sync(0xffffffffu, sv, o);
    }
    float ru = rsqrtf(su); ru = ru * (1.5f - 0.5f * su * ru * ru);
    float rv = rsqrtf(sv); rv = rv * (1.5f - 0.5f * sv * rv * rv);

    float2 un = make_float2(u.x * ru, u.y * ru);
    float2 vn = make_float2(v.x * rv, v.y * rv);

    __half2 uh = __float22half2_rn(un);
    __half2 vh = __float22half2_rn(vn);
    int idx = row * 32 + lane;
    g_h16[0][idx] = *reinterpret_cast<unsigned int*>(&uh);
    g_h16[1][idx] = *reinterpret_cast<unsigned int*>(&vh);

    float dx = un.x - vn.x, dy = un.y - vn.y;
    float a = dx * dx + dy * dy;
    #pragma unroll
    for (int o = 16; o > 0; o >>= 1)
        a += __shfl_xor_sync(0xffffffffu, a, o);
    if (lane == 0) g_align[row] = a;
}

// ---------------------------------------------------------------------------
// Kernel 2: one 128x128 Gram tile-pair per CTA via mma.sync fp16.
// grid = (NPAIRS, 2); triangular tile enumeration (bi >= bj), diagonal tiles
// masked to j < i. 8 warps in a 2x4 (m x n) layout: each warp owns 64x32.
// Rows padded to 72 halfs (144 B) -> ldmatrix phases hit 8 distinct banks.
// ---------------------------------------------------------------------------
__global__ void __launch_bounds__(256, 2) k_pair()
{
    __shared__ __align__(16) __half Ash[TILE][72];
    __shared__ __align__(16) __half Bsh[TILE][72];
    __shared__ float red[256];

    const int t   = blockIdx.x;
    const int mat = blockIdx.y;

    int bi = (int)((sqrtf(8.0f * (float)t + 1.0f) - 1.0f) * 0.5f);
    while ((bi + 1) * (bi + 2) / 2 <= t) ++bi;
    while (bi * (bi + 1) / 2 > t) --bi;
    const int bj   = t - bi * (bi + 1) / 2;
    const bool diag = (bi == bj);
    const int ibase = bi * TILE;
    const int jbase = bj * TILE;

    const int tid  = threadIdx.x;
    const int wid  = tid >> 5;
    const int lane = tid & 31;

    // tile loads: 128 rows x 8 uint4 chunks per tile
    const uint4* src = (const uint4*)g_h16[mat];
    #pragma unroll
    for (int r = 0; r < 4; ++r) {
        int idx = tid + 256 * r;        // 0..1023
        int row = idx >> 3;
        int ch  = idx & 7;
        *(uint4*)&Ash[row][ch * 8] = src[(ibase + row) * 8 + ch];
        *(uint4*)&Bsh[row][ch * 8] = src[(jbase + row) * 8 + ch];
    }
    __syncthreads();

    const int wm = wid & 1;             // m-slice (2 x 64)
    const int wn = wid >> 1;            // n-slice (4 x 32)
    const int m0 = wm * 64;
    const int n0 = wn * 32;

    float acc[4][4][4];
    #pragma unroll
    for (int mf = 0; mf < 4; ++mf)
        #pragma unroll
        for (int nf = 0; nf < 4; ++nf)
            #pragma unroll
            for (int r = 0; r < 4; ++r) acc[mf][nf][r] = 0.0f;

    // ldmatrix lane address components
    const int a_row = (lane & 15);          // + m0 + mf*16
    const int a_kc  = (lane >> 4) * 8;      // k chunk select
    const int b_row = ((lane >> 4) & 1) * 8 + (lane & 7);   // + n0 + nb*16
    const int b_kc  = ((lane >> 3) & 1) * 8;

    #pragma unroll
    for (int ks = 0; ks < 4; ++ks) {
        const int k0 = ks * 16;
        uint32_t A[4][4];
        #pragma unroll
        for (int mf = 0; mf < 4; ++mf) {
            uint32_t ad = (uint32_t)__cvta_generic_to_shared(
                &Ash[m0 + mf * 16 + a_row][k0 + a_kc]);
            ldsm4(A[mf], ad);
        }
        uint32_t B[2][4];
        #pragma unroll
        for (int nb = 0; nb < 2; ++nb) {
            uint32_t bd = (uint32_t)__cvta_generic_to_shared(
                &Bsh[n0 + nb * 16 + b_row][k0 + b_kc]);
            ldsm4(B[nb], bd);
        }
        #pragma unroll
        for (int mf = 0; mf < 4; ++mf)
            #pragma unroll
            for (int nf = 0; nf < 4; ++nf)
                mma16816(acc[mf][nf], A[mf],
                         B[nf >> 1][(nf & 1) * 2], B[nf >> 1][(nf & 1) * 2 + 1]);
    }

    // epilogue: exp(-2*max(2-2d,0)) = exp(4*min(d,1)-4)
    float s = 0.0f;
    #pragma unroll
    for (int mf = 0; mf < 4; ++mf) {
        const int gi0 = ibase + m0 + mf * 16 + (lane >> 2);
        #pragma unroll
        for (int nf = 0; nf < 4; ++nf) {
            const int gj0 = jbase + n0 + nf * 8 + (lane & 3) * 2;
            const float* d = acc[mf][nf];
            // reg r: row = gi0 + (r>=2 ? 8 : 0), col = gj0 + (r&1)
            #pragma unroll
            for (int r = 0; r < 4; ++r) {
                int gi = gi0 + ((r >> 1) << 3);
                int gj = gj0 + (r & 1);
                float term = __expf(fminf(d[r], 1.0f) * 4.0f - 4.0f);
                if (!diag || gj < gi) s += term;
            }
        }
    }

    red[tid] = s;
    __syncthreads();
    #pragma unroll
    for (int o = 128; o > 0; o >>= 1) {
        if (tid < o) red[tid] += red[tid + o];
        __syncthreads();
    }
    if (tid == 0) g_S[mat * NPAIRS + t] = red[0];
}

// ---------------------------------------------------------------------------
// Kernel 3: deterministic final reduction + scalar assembly.
// ---------------------------------------------------------------------------
__device__ __forceinline__ float block_sum(const float* src, int n,
                                           float* red, int tid)
{
    float a = 0.0f;
    for (int i = tid; i < n; i += 256) a += src[i];
    red[tid] = a;
    __syncthreads();
    #pragma unroll
    for (int o = 128; o > 0; o >>= 1) {
        if (tid < o) red[tid] += red[tid + o];
        __syncthreads();
    }
    float r = red[0];
    __syncthreads();
    return r;
}

__global__ void k_final(float* __restrict__ out)
{
    __shared__ float red[256];
    int tid = threadIdx.x;

    float align_sum = block_sum(g_align, NROWS, red, tid);
    float su        = block_sum(g_S, NPAIRS, red, tid);
    float si        = block_sum(g_S + NPAIRS, NPAIRS, red, tid);

    if (tid == 0) {
        const float denom = (float)NROWS * (float)(NROWS - 1);
        float align  = align_sum / (float)NROWS;
        float log_u  = logf(2.0f * su / denom + EPS_U);
        float log_i  = logf(2.0f * si / denom + EPS_U);
        out[0] = align + 0.5f * (log_u + log_i);   // GAMMA = 1
    }
}

extern "C" void kernel_launch(void* const* d_in, const int* in_sizes, int n_in,
                              void* d_out, int out_size)
{
    const float* U = (const float*)d_in[0];
    const float* I = (const float*)d_in[1];
    float* out = (float*)d_out;

    k_norm_align<<<NROWS / 8, 256>>>(U, I);
    dim3 grid(NPAIRS, 2, 1);
    k_pair<<<grid, 256>>>();
    k_final<<<1, 256>>>(out);
}

// round 9
// speedup vs baseline: 5.1432x; 1.2159x over previous
#include <cuda_runtime.h>
#include <cuda_fp16.h>
#include <math.h>
#include <cstdint>

// DirectAU loss: align + uniformity on N=8192, D=64 fp32 vectors.
//   align   = mean_i ||u_hat_i - i_hat_i||^2
//   uniform = (log(2*S_u/(N(N-1)) + eps) + log(2*S_i/(N(N-1)) + eps)) / 2
//   where S = sum_{i>j} exp(-2 * max(2 - 2 <x_i, x_j>, 0))
//
// R8: persistent k_pair (304 CTAs, stride loop), cp.async next-tile loads
// overlapped with the exp epilogue, epilogue trimmed to FFMA+EX2+FADD per
// term (clamp dropped off-diagonal: <x_i,x_j> <= 1 for unit vectors, and the
// max off-diag cosine of 33M random 64-dim pairs is ~0.74, so max(2-2d,0)
// never clamps there; diagonal tiles keep the guarded path).

#define NROWS  8192
#define DDIM   64
#define TILE   128
#define NTILES 64
#define NPAIRS 2080            // NTILES*(NTILES+1)/2
#define NWORK  (2 * NPAIRS)
#define EPS_U  1e-8f
#define GRID_PAIR 304          // 2 CTAs per SM (152 SMs on GB300)

__device__ float g_align[NROWS];
__device__ float g_S[NWORK];
__device__ unsigned int g_h16[2][NROWS * 32];   // fp16x2-packed normalized rows

// ---------------------------------------------------------------------------
// PTX helpers
// ---------------------------------------------------------------------------
__device__ __forceinline__ void ldsm4(uint32_t* r, uint32_t addr) {
    asm volatile("ldmatrix.sync.aligned.m8n8.x4.shared.b16 {%0,%1,%2,%3}, [%4];"
                 : "=r"(r[0]), "=r"(r[1]), "=r"(r[2]), "=r"(r[3]) : "r"(addr));
}
__device__ __forceinline__ void mma16816(float* d, const uint32_t* a,
                                         uint32_t b0, uint32_t b1) {
    asm volatile("mma.sync.aligned.m16n8k16.row.col.f32.f16.f16.f32 "
                 "{%0,%1,%2,%3},{%4,%5,%6,%7},{%8,%9},{%0,%1,%2,%3};"
                 : "+f"(d[0]), "+f"(d[1]), "+f"(d[2]), "+f"(d[3])
                 : "r"(a[0]), "r"(a[1]), "r"(a[2]), "r"(a[3]), "r"(b0), "r"(b1));
}
__device__ __forceinline__ void cp16(uint32_t saddr, const void* g) {
    asm volatile("cp.async.cg.shared.global [%0], [%1], 16;"
                 :: "r"(saddr), "l"(g) : "memory");
}
__device__ __forceinline__ float ex2f(float z) {
    float e;
    asm("ex2.approx.ftz.f32 %0, %1;" : "=f"(e) : "f"(z));
    return e;
}

// ---------------------------------------------------------------------------
// Kernel 1: normalize both matrices, per-row alignment, fp16 pack.
// ---------------------------------------------------------------------------
__global__ void __launch_bounds__(256) k_norm_align(const float* __restrict__ U,
                                                    const float* __restrict__ I)
{
    int warp = threadIdx.x >> 5;
    int lane = threadIdx.x & 31;
    int row  = blockIdx.x * 8 + warp;

    float2 u = ((const float2*)U)[row * 32 + lane];
    float2 v = ((const float2*)I)[row * 32 + lane];

    float su = u.x * u.x + u.y * u.y;
    float sv = v.x * v.x + v.y * v.y;
    #pragma unroll
    for (int o = 16; o > 0; o >>= 1) {
        su += __shfl_xor_sync(0xffffffffu, su, o);
        sv += __shfl_xor_sync(0xffffffffu, sv, o);
    }
    float ru = rsqrtf(su); ru = ru * (1.5f - 0.5f * su * ru * ru);
    float rv = rsqrtf(sv); rv = rv * (1.5f - 0.5f * sv * rv * rv);

    float2 un = make_float2(u.x * ru, u.y * ru);
    float2 vn = make_float2(v.x * rv, v.y * rv);

    __half2 uh = __float22half2_rn(un);
    __half2 vh = __float22half2_rn(vn);
    int idx = row * 32 + lane;
    g_h16[0][idx] = *reinterpret_cast<unsigned int*>(&uh);
    g_h16[1][idx] = *reinterpret_cast<unsigned int*>(&vh);

    float dx = un.x - vn.x, dy = un.y - vn.y;
    float a = dx * dx + dy * dy;
    #pragma unroll
    for (int o = 16; o > 0; o >>= 1)
        a += __shfl_xor_sync(0xffffffffu, a, o);
    if (lane == 0) g_align[row] = a;
}

// ---------------------------------------------------------------------------
// Kernel 2: persistent Gram tile-pair worker.
// Work item w -> (mat, triangular tile (bi,bj)). 8 warps in 2x4 layout, each
// warp 64x32 of the 128x128 tile. Rows padded to 72 halfs for ldmatrix.
// ---------------------------------------------------------------------------
__device__ __forceinline__ void decode_work(int w, int& mat, int& ibase,
                                            int& jbase, bool& diag)
{
    mat = (w >= NPAIRS) ? 1 : 0;
    int t = w - mat * NPAIRS;
    int bi = (int)((sqrtf(8.0f * (float)t + 1.0f) - 1.0f) * 0.5f);
    while ((bi + 1) * (bi + 2) / 2 <= t) ++bi;
    while (bi * (bi + 1) / 2 > t) --bi;
    int bj = t - bi * (bi + 1) / 2;
    diag  = (bi == bj);
    ibase = bi * TILE;
    jbase = bj * TILE;
}

__global__ void __launch_bounds__(256, 2) k_pair()
{
    __shared__ __align__(16) __half Ash[TILE][72];
    __shared__ __align__(16) __half Bsh[TILE][72];
    __shared__ float red[8];

    const int tid  = threadIdx.x;
    const int wid  = tid >> 5;
    const int lane = tid & 31;

    // per-thread load slots: 4 x (row, chunk), 16B cp.async each per tile
    int l_row[4], l_ch[4];
    uint32_t sA[4], sB[4];
    #pragma unroll
    for (int r = 0; r < 4; ++r) {
        int idx  = tid + 256 * r;
        l_row[r] = idx >> 3;
        l_ch[r]  = idx & 7;
        sA[r] = (uint32_t)__cvta_generic_to_shared(&Ash[l_row[r]][l_ch[r] * 8]);
        sB[r] = (uint32_t)__cvta_generic_to_shared(&Bsh[l_row[r]][l_ch[r] * 8]);
    }

    const int wm = wid & 1;
    const int wn = wid >> 1;
    const int m0 = wm * 64;
    const int n0 = wn * 32;
    const int a_row = (lane & 15);
    const int a_kc  = (lane >> 4) * 8;
    const int b_row = ((lane >> 4) & 1) * 8 + (lane & 7);
    const int b_kc  = ((lane >> 3) & 1) * 8;

    int w = blockIdx.x;
    int mat, ibase, jbase; bool diag;
    if (w < NWORK) {
        decode_work(w, mat, ibase, jbase, diag);
        const uint4* src = (const uint4*)g_h16[mat];
        #pragma unroll
        for (int r = 0; r < 4; ++r) {
            cp16(sA[r], &src[(ibase + l_row[r]) * 8 + l_ch[r]]);
            cp16(sB[r], &src[(jbase + l_row[r]) * 8 + l_ch[r]]);
        }
        asm volatile("cp.async.commit_group;" ::: "memory");
    }

    while (w < NWORK) {
        asm volatile("cp.async.wait_group 0;" ::: "memory");
        __syncthreads();

        // mainloop: 4 k-steps of 16, ldmatrix + mma.sync fp16
        float acc[4][4][4];
        #pragma unroll
        for (int mf = 0; mf < 4; ++mf)
            #pragma unroll
            for (int nf = 0; nf < 4; ++nf)
                #pragma unroll
                for (int r = 0; r < 4; ++r) acc[mf][nf][r] = 0.0f;

        #pragma unroll
        for (int ks = 0; ks < 4; ++ks) {
            const int k0 = ks * 16;
            uint32_t A[4][4];
            #pragma unroll
            for (int mf = 0; mf < 4; ++mf) {
                uint32_t ad = (uint32_t)__cvta_generic_to_shared(
                    &Ash[m0 + mf * 16 + a_row][k0 + a_kc]);
                ldsm4(A[mf], ad);
            }
            uint32_t B[2][4];
            #pragma unroll
            for (int nb = 0; nb < 2; ++nb) {
                uint32_t bd = (uint32_t)__cvta_generic_to_shared(
                    &Bsh[n0 + nb * 16 + b_row][k0 + b_kc]);
                ldsm4(B[nb], bd);
            }
            #pragma unroll
            for (int mf = 0; mf < 4; ++mf)
                #pragma unroll
                for (int nf = 0; nf < 4; ++nf)
                    mma16816(acc[mf][nf], A[mf],
                             B[nf >> 1][(nf & 1) * 2], B[nf >> 1][(nf & 1) * 2 + 1]);
        }
        __syncthreads();                  // all warps done reading tiles

        // issue next tile's loads; they land during the epilogue below
        const int wn_next = w + gridDim.x;
        if (wn_next < NWORK) {
            int nmat, nib, njb; bool nd;
            decode_work(wn_next, nmat, nib, njb, nd);
            const uint4* src = (const uint4*)g_h16[nmat];
            #pragma unroll
            for (int r = 0; r < 4; ++r) {
                cp16(sA[r], &src[(nib + l_row[r]) * 8 + l_ch[r]]);
                cp16(sB[r], &src[(njb + l_row[r]) * 8 + l_ch[r]]);
            }
            asm volatile("cp.async.commit_group;" ::: "memory");
        }

        // epilogue: term = exp(4d-4) = ex2(d*K2 - K2), K2 = 4*log2(e).
        // Off-diagonal: no clamp needed (d <= 1 up to fp16 noise, clamp
        // inactive for this distribution). Diagonal: clamp + j<i mask.
        const float K2 = 5.7707801635558535f;
        float s = 0.0f;
        if (!diag) {
            #pragma unroll
            for (int mf = 0; mf < 4; ++mf)
                #pragma unroll
                for (int nf = 0; nf < 4; ++nf) {
                    const float* d = acc[mf][nf];
                    #pragma unroll
                    for (int r = 0; r < 4; ++r)
                        s += ex2f(fmaf(d[r], K2, -K2));
                }
        } else {
            #pragma unroll
            for (int mf = 0; mf < 4; ++mf) {
                const int gi0 = ibase + m0 + mf * 16 + (lane >> 2);
                #pragma unroll
                for (int nf = 0; nf < 4; ++nf) {
                    const int gj0 = jbase + n0 + nf * 8 + (lane & 3) * 2;
                    const float* d = acc[mf][nf];
                    #pragma unroll
                    for (int r = 0; r < 4; ++r) {
                        int gi = gi0 + ((r >> 1) << 3);
                        int gj = gj0 + (r & 1);
                        float term = ex2f(fminf(d[r], 1.0f) * K2 - K2);
                        if (gj < gi) s += term;
                    }
                }
            }
        }

        // warp shfl-reduce, then cross-warp pass
        #pragma unroll
        for (int o = 16; o > 0; o >>= 1)
            s += __shfl_xor_sync(0xffffffffu, s, o);
        if (lane == 0) red[wid] = s;
        __syncthreads();
        if (tid == 0) {
            float tot = 0.0f;
            #pragma unroll
            for (int i = 0; i < 8; ++i) tot += red[i];
            g_S[w] = tot;
        }

        w = wn_next;
        if (w < NWORK) decode_work(w, mat, ibase, jbase, diag);
    }
}

// ---------------------------------------------------------------------------
// Kernel 3: deterministic final reduction + scalar assembly.
// ---------------------------------------------------------------------------
__device__ __forceinline__ float block_sum(const float* src, int n,
                                           float* red, int tid)
{
    float a = 0.0f;
    for (int i = tid; i < n; i += 256) a += src[i];
    red[tid] = a;
    __syncthreads();
    #pragma unroll
    for (int o = 128; o > 0; o >>= 1) {
        if (tid < o) red[tid] += red[tid + o];
        __syncthreads();
    }
    float r = red[0];
    __syncthreads();
    return r;
}

__global__ void k_final(float* __restrict__ out)
{
    __shared__ float red[256];
    int tid = threadIdx.x;

    float align_sum = block_sum(g_align, NROWS, red, tid);
    float su        = block_sum(g_S, NPAIRS, red, tid);
    float si        = block_sum(g_S + NPAIRS, NPAIRS, red, tid);

    if (tid == 0) {
        const float denom = (float)NROWS * (float)(NROWS - 1);
        float align  = align_sum / (float)NROWS;
        float log_u  = logf(2.0f * su / denom + EPS_U);
        float log_i  = logf(2.0f * si / denom + EPS_U);
        out[0] = align + 0.5f * (log_u + log_i);   // GAMMA = 1
    }
}

extern "C" void kernel_launch(void* const* d_in, const int* in_sizes, int n_in,
                              void* d_out, int out_size)
{
    const float* U = (const float*)d_in[0];
    const float* I = (const float*)d_in[1];
    float* out = (float*)d_out;

    k_norm_align<<<NROWS / 8, 256>>>(U, I);
    k_pair<<<GRID_PAIR, 256>>>();
    k_final<<<1, 256>>>(out);
}